// round 10
// baseline (speedup 1.0000x reference)
#include <cuda_runtime.h>
#include <cuda_bf16.h>
#include <math.h>
#include <stdint.h>

#define BATCH 4096
#define DIM   256
#define NPAIR 6
#define INV_T 10.0f
#define FP8_SCALE 16.0f
// logits = acc * INV_T / (FP8_SCALE*FP8_SCALE)
#define ACC_TO_LOGIT (INV_T / (FP8_SCALE * FP8_SCALE))

__constant__ int c_pi[NPAIR] = {0, 0, 0, 1, 1, 2};
__constant__ int c_pj[NPAIR] = {1, 2, 3, 2, 3, 3};

// Scratch (allocs forbidden)
__device__ uint8_t g_znf8[4 * BATCH * DIM];        // normalized*16, e4m3 (4.2MB)
__device__ float g_rowsum[NPAIR * BATCH];
__device__ float g_colsum[NPAIR * BATCH];
__device__ float g_diag[NPAIR * BATCH];

// ---------------------------------------------------------------------------
__device__ __forceinline__ uint32_t smem_u32(const void* p) {
    uint32_t a;
    asm("{ .reg .u64 t; cvta.to.shared.u64 t, %1; cvt.u32.u64 %0, t; }"
        : "=r"(a) : "l"(p));
    return a;
}

#define CP_ASYNC16(smem, gptr) \
    asm volatile("cp.async.cg.shared.global [%0], [%1], 16;" \
                 :: "r"(smem), "l"(gptr) : "memory")
#define CP_COMMIT() asm volatile("cp.async.commit_group;" ::: "memory")
#define CP_WAIT(n)  asm volatile("cp.async.wait_group %0;" :: "n"(n) : "memory")

#define LDMATRIX_X4(r0, r1, r2, r3, addr) \
    asm volatile("ldmatrix.sync.aligned.m8n8.x4.shared.b16 {%0,%1,%2,%3}, [%4];" \
                 : "=r"(r0), "=r"(r1), "=r"(r2), "=r"(r3) : "r"(addr))

// e4m3 x e4m3 -> f32, m16n8k32. Same register signature as bf16 m16n8k16.
#define MMA_FP8(c, a, b) \
    asm volatile("mma.sync.aligned.m16n8k32.row.col.f32.e4m3.e4m3.f32 " \
                 "{%0,%1,%2,%3}, {%4,%5,%6,%7}, {%8,%9}, {%0,%1,%2,%3};" \
                 : "+f"((c)[0]), "+f"((c)[1]), "+f"((c)[2]), "+f"((c)[3]) \
                 : "r"((a)[0]), "r"((a)[1]), "r"((a)[2]), "r"((a)[3]), \
                   "r"((b)[0]), "r"((b)[1]))

// pack two floats -> e4m3x2 (lo in low byte)
__device__ __forceinline__ uint16_t pack_e4m3x2(float lo, float hi) {
    uint16_t r;
    asm("cvt.rn.satfinite.e4m3x2.f32 %0, %1, %2;" : "=h"(r) : "f"(hi), "f"(lo));
    return r;
}

// ---------------------------------------------------------------------------
// Kernels 0a/0b: split zeroing (keeps pair_mma at launch index 3 for ncu).
// ---------------------------------------------------------------------------
__global__ void zero_row_kernel(float* out) {
    int idx = blockIdx.x * blockDim.x + threadIdx.x;
    if (idx < NPAIR * BATCH) g_rowsum[idx] = 0.0f;
    if (idx == 0) out[0] = 0.0f;
}
__global__ void zero_col_kernel() {
    int idx = blockIdx.x * blockDim.x + threadIdx.x;
    if (idx < NPAIR * BATCH) g_colsum[idx] = 0.0f;
}

// ---------------------------------------------------------------------------
// Kernel 1: L2-normalize -> e4m3 * 16. Two rows per warp (MLP 4).
// ---------------------------------------------------------------------------
__global__ void normalize_kernel(const float* __restrict__ z0,
                                 const float* __restrict__ z1,
                                 const float* __restrict__ z2,
                                 const float* __restrict__ z3) {
    int gidx = blockIdx.x * blockDim.x + threadIdx.x;
    int gwarp = gidx >> 5;                 // 0 .. 2*BATCH-1
    int lane  = threadIdx.x & 31;
    if (gwarp >= 2 * BATCH) return;

    float4 v[2][2];
    float  ss[2];
    const float* srcs[2];
#pragma unroll
    for (int r = 0; r < 2; r++) {
        int fr   = gwarp * 2 + r;          // flat row 0..16383
        int view = fr >> 12;
        int row  = fr & (BATCH - 1);
        const float* src;
        switch (view) {
            case 0: src = z0; break;
            case 1: src = z1; break;
            case 2: src = z2; break;
            default: src = z3; break;
        }
        srcs[r] = src + (size_t)row * DIM;
    }
#pragma unroll
    for (int r = 0; r < 2; r++) {
        const float4* s4 = (const float4*)srcs[r];
        v[r][0] = s4[lane * 2 + 0];
        v[r][1] = s4[lane * 2 + 1];
    }
#pragma unroll
    for (int r = 0; r < 2; r++) {
        float4 a = v[r][0], b = v[r][1];
        ss[r] = a.x * a.x + a.y * a.y + a.z * a.z + a.w * a.w
              + b.x * b.x + b.y * b.y + b.z * b.z + b.w * b.w;
    }
#pragma unroll
    for (int o = 16; o > 0; o >>= 1) {
        ss[0] += __shfl_xor_sync(0xFFFFFFFFu, ss[0], o);
        ss[1] += __shfl_xor_sync(0xFFFFFFFFu, ss[1], o);
    }
#pragma unroll
    for (int r = 0; r < 2; r++) {
        float inv = FP8_SCALE / fmaxf(sqrtf(ss[r]), 1e-8f);
        float4 a = v[r][0], b = v[r][1];
        uint16_t q0 = pack_e4m3x2(a.x * inv, a.y * inv);
        uint16_t q1 = pack_e4m3x2(a.z * inv, a.w * inv);
        uint16_t q2 = pack_e4m3x2(b.x * inv, b.y * inv);
        uint16_t q3 = pack_e4m3x2(b.z * inv, b.w * inv);
        uint2 o2;
        o2.x = (uint32_t)q0 | ((uint32_t)q1 << 16);
        o2.y = (uint32_t)q2 | ((uint32_t)q3 << 16);
        int fr = gwarp * 2 + r;
        uint2* dst = (uint2*)(g_znf8 + (size_t)fr * DIM);
        dst[lane] = o2;     // 8 bytes: columns lane*8 .. lane*8+7
    }
}

// ---------------------------------------------------------------------------
// Kernel 2 (launch index 3): FP8 mma.sync pair GEMM + exp + sums + diag.
// CTA tile 128x128, 8 warps 4x2, warp tile 32x64 (proven core, byte-identical
// addressing). K = 256 fp8 = 2 chunks of 128 fp8 (128-byte rows). Everything
// loaded in the prologue (2 cp.async groups, 64 KB) -> no mid-loop loads,
// 2 barriers total.
// SMEM chunk layout (128 rows x 128 fp8, 16 KB):
//   element (row, k): byte = row*128 + ((k/16) ^ (row&7))*16 + (k%16)
// ---------------------------------------------------------------------------
#define KC 128                      // fp8 k per chunk
#define CHUNK_BYTES (128 * 128)     // 16 KB
#define NCHUNK 2
#define SMEM_TOTAL (2 * NCHUNK * CHUNK_BYTES)   // 64 KB

__device__ __forceinline__ void load_chunk(uint32_t s_base,
                                           const uint8_t* __restrict__ src,
                                           int kc, int tid) {
#pragma unroll
    for (int it = 0; it < 4; it++) {
        int idx = it * 256 + tid;         // 0..1023
        int row = idx >> 3;
        int c   = idx & 7;                // 16B granule within 128B row
        const uint8_t* g = src + (size_t)row * DIM + kc * KC + c * 16;
        uint32_t s = s_base + row * 128 + ((c ^ (row & 7)) << 4);
        CP_ASYNC16(s, g);
    }
}

__global__ void __launch_bounds__(256) pair_mma_kernel() {
    extern __shared__ char smraw[];
    uint32_t sbase = smem_u32(smraw);

    int tid = threadIdx.x;
    int w = tid >> 5, lane = tid & 31;
    int warp_m = w & 3;                 // 0..3 -> 32 rows each
    int warp_n = w >> 2;                // 0..1 -> 64 cols each

    int p = blockIdx.z;
    int rowBase = blockIdx.y * 128;
    int colBase = blockIdx.x * 128;
    const uint8_t* Asrc = g_znf8 + ((size_t)c_pi[p] * BATCH + rowBase) * DIM;
    const uint8_t* Bsrc = g_znf8 + ((size_t)c_pj[p] * BATCH + colBase) * DIM;

    uint32_t sA[NCHUNK], sB[NCHUNK];
#pragma unroll
    for (int s = 0; s < NCHUNK; s++) {
        sA[s] = sbase + s * CHUNK_BYTES;
        sB[s] = sbase + (NCHUNK + s) * CHUNK_BYTES;
    }

    // Prologue: chunk 0 (group 0), chunk 1 (group 1) — that's ALL the data.
    load_chunk(sA[0], Asrc, 0, tid);
    load_chunk(sB[0], Bsrc, 0, tid);
    CP_COMMIT();
    load_chunk(sA[1], Asrc, 1, tid);
    load_chunk(sB[1], Bsrc, 1, tid);
    CP_COMMIT();

    float c[2][8][4];
#pragma unroll
    for (int i = 0; i < 2; i++)
#pragma unroll
        for (int j = 0; j < 8; j++)
#pragma unroll
            for (int q = 0; q < 4; q++) c[i][j][q] = 0.0f;

    // lane addressing, byte-identical to the proven bf16 version:
    int ar = warp_m * 32 + (lane & 15);
    int akg = lane >> 4;
    int bn = warp_n * 64 + ((lane >> 4) << 3) + (lane & 7);
    int bkg = (lane >> 3) & 1;

#pragma unroll
    for (int kc = 0; kc < NCHUNK; kc++) {
        if (kc == 0) { CP_WAIT(1); } else { CP_WAIT(0); }
        __syncthreads();

#pragma unroll
        for (int kk = 0; kk < 4; kk++) {       // 4 x k32 per 128-fp8 chunk
            uint32_t a[2][4];
#pragma unroll
            for (int fm = 0; fm < 2; fm++) {
                int r = ar + fm * 16;
                int kg = kk * 2 + akg;
                uint32_t addr = sA[kc] + r * 128 + ((kg ^ (r & 7)) << 4);
                LDMATRIX_X4(a[fm][0], a[fm][1], a[fm][2], a[fm][3], addr);
            }
            uint32_t b[4][4];
#pragma unroll
            for (int nb = 0; nb < 4; nb++) {
                int n = bn + nb * 16;
                int kg = kk * 2 + bkg;
                uint32_t addr = sB[kc] + n * 128 + ((kg ^ (n & 7)) << 4);
                LDMATRIX_X4(b[nb][0], b[nb][1], b[nb][2], b[nb][3], addr);
            }
#pragma unroll
            for (int fm = 0; fm < 2; fm++)
#pragma unroll
                for (int nb = 0; nb < 4; nb++) {
                    uint32_t bf0[2] = {b[nb][0], b[nb][1]};
                    uint32_t bf1[2] = {b[nb][2], b[nb][3]};
                    MMA_FP8(c[fm][nb * 2 + 0], a[fm], bf0);
                    MMA_FP8(c[fm][nb * 2 + 1], a[fm], bf1);
                }
        }
    }

    // ------------------- epilogue (register-only) --------------------------
    // element (fm, fn, i, j): row = rowBase + warp_m*32 + fm*16 + i*8 + lane/4
    //                         col = colBase + warp_n*64 + fn*8 + (lane&3)*2 + j
    bool diag_cta = (rowBase == colBase);
    float rsum[2][2] = {{0, 0}, {0, 0}};
    float csum[16];
#pragma unroll
    for (int i = 0; i < 16; i++) csum[i] = 0.0f;

#pragma unroll
    for (int fm = 0; fm < 2; fm++)
#pragma unroll
        for (int fn = 0; fn < 8; fn++)
#pragma unroll
            for (int q = 0; q < 4; q++) {
                int i = q >> 1, j = q & 1;
                float s = c[fm][fn][q] * ACC_TO_LOGIT;
                float e = __expf(s);
                rsum[fm][i] += e;
                csum[fn * 2 + j] += e;
                if (diag_cta) {
                    int gr = rowBase + warp_m * 32 + fm * 16 + i * 8 + (lane >> 2);
                    int gc = colBase + warp_n * 64 + fn * 8 + (lane & 3) * 2 + j;
                    if (gr == gc) g_diag[p * BATCH + gr] = s;
                }
            }

#pragma unroll
    for (int fm = 0; fm < 2; fm++)
#pragma unroll
        for (int i = 0; i < 2; i++) {
            float v = rsum[fm][i];
            v += __shfl_xor_sync(0xFFFFFFFFu, v, 1);
            v += __shfl_xor_sync(0xFFFFFFFFu, v, 2);
            if ((lane & 3) == 0) {
                int gr = rowBase + warp_m * 32 + fm * 16 + i * 8 + (lane >> 2);
                atomicAdd(&g_rowsum[p * BATCH + gr], v);
            }
        }

#pragma unroll
    for (int t = 0; t < 16; t++) {
        float v = csum[t];
        v += __shfl_xor_sync(0xFFFFFFFFu, v, 4);
        v += __shfl_xor_sync(0xFFFFFFFFu, v, 8);
        v += __shfl_xor_sync(0xFFFFFFFFu, v, 16);
        if (lane < 4) {
            int fn = t >> 1, j = t & 1;
            int gc = colBase + warp_n * 64 + fn * 8 + lane * 2 + j;
            atomicAdd(&g_colsum[p * BATCH + gc], v);
        }
    }
}

// ---------------------------------------------------------------------------
// Kernel 3: per-(pair,b) loss terms + global mean
// ---------------------------------------------------------------------------
__global__ void finalize_kernel(float* __restrict__ out) {
    int idx = blockIdx.x * 256 + threadIdx.x;
    float v = 0.0f;
    if (idx < NPAIR * BATCH)
        v = 0.5f * (logf(g_rowsum[idx]) + logf(g_colsum[idx])) - g_diag[idx];
#pragma unroll
    for (int o = 16; o > 0; o >>= 1)
        v += __shfl_xor_sync(0xFFFFFFFFu, v, o);
    __shared__ float ws[8];
    int w = threadIdx.x >> 5, l = threadIdx.x & 31;
    if (l == 0) ws[w] = v;
    __syncthreads();
    if (threadIdx.x == 0) {
        float s = 0.0f;
#pragma unroll
        for (int i = 0; i < 8; i++) s += ws[i];
        atomicAdd(out, s * (1.0f / ((float)BATCH * (float)NPAIR)));
    }
}

// ---------------------------------------------------------------------------
extern "C" void kernel_launch(void* const* d_in, const int* in_sizes, int n_in,
                              void* d_out, int out_size) {
    const float* z0 = (const float*)d_in[0];
    const float* z1 = (const float*)d_in[1];
    const float* z2 = (const float*)d_in[2];
    const float* z3 = (const float*)d_in[3];
    float* out = (float*)d_out;
    (void)in_sizes; (void)n_in; (void)out_size;

    cudaFuncSetAttribute(pair_mma_kernel,
                         cudaFuncAttributeMaxDynamicSharedMemorySize, SMEM_TOTAL);

    // launch indices: 0 zero_row, 1 zero_col, 2 normalize,
    // 3 pair_mma (ncu capture), 4 finalize
    zero_row_kernel<<<(NPAIR * BATCH + 255) / 256, 256>>>(out);
    zero_col_kernel<<<(NPAIR * BATCH + 255) / 256, 256>>>();
    normalize_kernel<<<(2 * BATCH) / 8, 256>>>(z0, z1, z2, z3);
    dim3 ggrid(32, 32, NPAIR);
    pair_mma_kernel<<<ggrid, 256, SMEM_TOTAL>>>();
    finalize_kernel<<<(NPAIR * BATCH + 255) / 256, 256>>>(out);
}

// round 11
// speedup vs baseline: 1.5588x; 1.5588x over previous
#include <cuda_runtime.h>
#include <cuda_bf16.h>
#include <cuda_fp16.h>
#include <math.h>
#include <stdint.h>

#define BATCH 4096
#define DIM   256
#define NPAIR 6
#define INV_T 10.0f
// exp(s) = exp2(acc * INV_T * log2(e))
#define CEXP  (INV_T * 1.4426950408889634f)

__constant__ int c_pi[NPAIR] = {0, 0, 0, 1, 1, 2};
__constant__ int c_pj[NPAIR] = {1, 2, 3, 2, 3, 3};

// Scratch (allocs forbidden)
__device__ __nv_bfloat16 g_znb[4 * BATCH * DIM];   // normalized views, bf16
__device__ float g_rowsum[NPAIR * BATCH];
__device__ float g_colsum[NPAIR * BATCH];
__device__ float g_diag[NPAIR * BATCH];

// ---------------------------------------------------------------------------
__device__ __forceinline__ uint32_t smem_u32(const void* p) {
    uint32_t a;
    asm("{ .reg .u64 t; cvta.to.shared.u64 t, %1; cvt.u32.u64 %0, t; }"
        : "=r"(a) : "l"(p));
    return a;
}

#define CP_ASYNC16(smem, gptr) \
    asm volatile("cp.async.cg.shared.global [%0], [%1], 16;" \
                 :: "r"(smem), "l"(gptr) : "memory")
#define CP_COMMIT() asm volatile("cp.async.commit_group;" ::: "memory")
#define CP_WAIT(n)  asm volatile("cp.async.wait_group %0;" :: "n"(n) : "memory")

#define LDMATRIX_X4(r0, r1, r2, r3, addr) \
    asm volatile("ldmatrix.sync.aligned.m8n8.x4.shared.b16 {%0,%1,%2,%3}, [%4];" \
                 : "=r"(r0), "=r"(r1), "=r"(r2), "=r"(r3) : "r"(addr))

#define MMA_BF16(c, a, b) \
    asm volatile("mma.sync.aligned.m16n8k16.row.col.f32.bf16.bf16.f32 " \
                 "{%0,%1,%2,%3}, {%4,%5,%6,%7}, {%8,%9}, {%0,%1,%2,%3};" \
                 : "+f"((c)[0]), "+f"((c)[1]), "+f"((c)[2]), "+f"((c)[3]) \
                 : "r"((a)[0]), "r"((a)[1]), "r"((a)[2]), "r"((a)[3]), \
                   "r"((b)[0]), "r"((b)[1]))

// ---------------------------------------------------------------------------
// Kernels 0a/0b: split zeroing (keeps pair_mma at launch index 3 for ncu).
// ---------------------------------------------------------------------------
__global__ void zero_row_kernel(float* out) {
    int idx = blockIdx.x * blockDim.x + threadIdx.x;
    if (idx < NPAIR * BATCH) g_rowsum[idx] = 0.0f;
    if (idx == 0) out[0] = 0.0f;
}
__global__ void zero_col_kernel() {
    int idx = blockIdx.x * blockDim.x + threadIdx.x;
    if (idx < NPAIR * BATCH) g_colsum[idx] = 0.0f;
}

// ---------------------------------------------------------------------------
// Kernel 1: L2-normalize -> bf16. Two rows per warp (MLP 4).
// ---------------------------------------------------------------------------
__global__ void normalize_kernel(const float* __restrict__ z0,
                                 const float* __restrict__ z1,
                                 const float* __restrict__ z2,
                                 const float* __restrict__ z3) {
    int gidx = blockIdx.x * blockDim.x + threadIdx.x;
    int gwarp = gidx >> 5;                 // 0 .. 2*BATCH-1
    int lane  = threadIdx.x & 31;
    if (gwarp >= 2 * BATCH) return;

    float4 v[2][2];
    float  ss[2];
    const float* srcs[2];
#pragma unroll
    for (int r = 0; r < 2; r++) {
        int fr   = gwarp * 2 + r;          // flat row 0..16383
        int view = fr >> 12;
        int row  = fr & (BATCH - 1);
        const float* src;
        switch (view) {
            case 0: src = z0; break;
            case 1: src = z1; break;
            case 2: src = z2; break;
            default: src = z3; break;
        }
        srcs[r] = src + (size_t)row * DIM;
    }
#pragma unroll
    for (int r = 0; r < 2; r++) {
        const float4* s4 = (const float4*)srcs[r];
        v[r][0] = s4[lane * 2 + 0];
        v[r][1] = s4[lane * 2 + 1];
    }
#pragma unroll
    for (int r = 0; r < 2; r++) {
        float4 a = v[r][0], b = v[r][1];
        ss[r] = a.x * a.x + a.y * a.y + a.z * a.z + a.w * a.w
              + b.x * b.x + b.y * b.y + b.z * b.z + b.w * b.w;
    }
#pragma unroll
    for (int o = 16; o > 0; o >>= 1) {
        ss[0] += __shfl_xor_sync(0xFFFFFFFFu, ss[0], o);
        ss[1] += __shfl_xor_sync(0xFFFFFFFFu, ss[1], o);
    }
#pragma unroll
    for (int r = 0; r < 2; r++) {
        float inv = 1.0f / fmaxf(sqrtf(ss[r]), 1e-8f);
        float4 a = v[r][0], b = v[r][1];
        __nv_bfloat162 p0 = __floats2bfloat162_rn(a.x * inv, a.y * inv);
        __nv_bfloat162 p1 = __floats2bfloat162_rn(a.z * inv, a.w * inv);
        __nv_bfloat162 p2 = __floats2bfloat162_rn(b.x * inv, b.y * inv);
        __nv_bfloat162 p3 = __floats2bfloat162_rn(b.z * inv, b.w * inv);
        uint4 o4;
        o4.x = reinterpret_cast<uint32_t&>(p0);
        o4.y = reinterpret_cast<uint32_t&>(p1);
        o4.z = reinterpret_cast<uint32_t&>(p2);
        o4.w = reinterpret_cast<uint32_t&>(p3);
        int fr = gwarp * 2 + r;
        uint4* dst = (uint4*)(g_znb + (size_t)fr * DIM);
        dst[lane] = o4;
    }
}

// ---------------------------------------------------------------------------
// Kernel 2 (launch index 3): bf16 mma.sync pair GEMM (R6/R9 mainloop,
// verbatim) + optimized epilogue: exp2-folded scale + paired f16x2 exp.
// CTA tile 128x128, 8 warps 4x2, warp tile 32x64. K chunks of 64, 3-stage
// cp.async pipeline, one barrier per chunk.
// ---------------------------------------------------------------------------
#define KC 64
#define CHUNK_BYTES (128 * 128)     // 16 KB
#define NSTAGE 3
#define SMEM_TOTAL (2 * NSTAGE * CHUNK_BYTES)   // 96 KB

__device__ __forceinline__ void load_chunk(uint32_t s_base,
                                           const __nv_bfloat16* __restrict__ src,
                                           int kc, int tid) {
#pragma unroll
    for (int it = 0; it < 4; it++) {
        int idx = it * 256 + tid;         // 0..1023
        int row = idx >> 3;
        int c   = idx & 7;
        const __nv_bfloat16* g = src + (size_t)row * DIM + kc * KC + c * 8;
        uint32_t s = s_base + row * 128 + ((c ^ (row & 7)) << 4);
        CP_ASYNC16(s, g);
    }
}

__global__ void __launch_bounds__(256) pair_mma_kernel() {
    extern __shared__ char smraw[];
    uint32_t sbase = smem_u32(smraw);

    int tid = threadIdx.x;
    int w = tid >> 5, lane = tid & 31;
    int warp_m = w & 3;                 // 0..3 -> 32 rows each
    int warp_n = w >> 2;                // 0..1 -> 64 cols each

    int p = blockIdx.z;
    int rowBase = blockIdx.y * 128;
    int colBase = blockIdx.x * 128;
    const __nv_bfloat16* Asrc = g_znb + ((size_t)c_pi[p] * BATCH + rowBase) * DIM;
    const __nv_bfloat16* Bsrc = g_znb + ((size_t)c_pj[p] * BATCH + colBase) * DIM;

    uint32_t sA[NSTAGE], sB[NSTAGE];
#pragma unroll
    for (int s = 0; s < NSTAGE; s++) {
        sA[s] = sbase + s * CHUNK_BYTES;
        sB[s] = sbase + (NSTAGE + s) * CHUNK_BYTES;
    }

    float c[2][8][4];
#pragma unroll
    for (int i = 0; i < 2; i++)
#pragma unroll
        for (int j = 0; j < 8; j++)
#pragma unroll
            for (int q = 0; q < 4; q++) c[i][j][q] = 0.0f;

    int ar = warp_m * 32 + (lane & 15);
    int akg = lane >> 4;
    int bn = warp_n * 64 + ((lane >> 4) << 3) + (lane & 7);
    int bkg = (lane >> 3) & 1;

    load_chunk(sA[0], Asrc, 0, tid);
    load_chunk(sB[0], Bsrc, 0, tid);
    CP_COMMIT();
    load_chunk(sA[1], Asrc, 1, tid);
    load_chunk(sB[1], Bsrc, 1, tid);
    CP_COMMIT();

#pragma unroll
    for (int kc = 0; kc < 4; kc++) {
        if (kc < 3) { CP_WAIT(1); } else { CP_WAIT(0); }
        __syncthreads();
        if (kc < 2) {
            int nb = (kc + 2) % NSTAGE;
            load_chunk(sA[nb], Asrc, kc + 2, tid);
            load_chunk(sB[nb], Bsrc, kc + 2, tid);
            CP_COMMIT();
        }
        int buf = kc % NSTAGE;

#pragma unroll
        for (int kk = 0; kk < 4; kk++) {
            uint32_t a[2][4];
#pragma unroll
            for (int fm = 0; fm < 2; fm++) {
                int r = ar + fm * 16;
                int kg = kk * 2 + akg;
                uint32_t addr = sA[buf] + r * 128 + ((kg ^ (r & 7)) << 4);
                LDMATRIX_X4(a[fm][0], a[fm][1], a[fm][2], a[fm][3], addr);
            }
            uint32_t b[4][4];
#pragma unroll
            for (int nb = 0; nb < 4; nb++) {
                int n = bn + nb * 16;
                int kg = kk * 2 + bkg;
                uint32_t addr = sB[buf] + n * 128 + ((kg ^ (n & 7)) << 4);
                LDMATRIX_X4(b[nb][0], b[nb][1], b[nb][2], b[nb][3], addr);
            }
#pragma unroll
            for (int fm = 0; fm < 2; fm++)
#pragma unroll
                for (int nb = 0; nb < 4; nb++) {
                    uint32_t bf0[2] = {b[nb][0], b[nb][1]};
                    uint32_t bf1[2] = {b[nb][2], b[nb][3]};
                    MMA_BF16(c[fm][nb * 2 + 0], a[fm], bf0);
                    MMA_BF16(c[fm][nb * 2 + 1], a[fm], bf1);
                }
        }
    }

    // ------------------- epilogue (f16x2 paired exp) -----------------------
    // element (fm, fn, i, j): row = rowBase + warp_m*32 + fm*16 + i*8 + lane/4
    //                         col = colBase + warp_n*64 + fn*8 + (lane&3)*2 + j
    bool diag_cta = (rowBase == colBase);
    float rsum[2][2] = {{0, 0}, {0, 0}};
    float csum[16];
#pragma unroll
    for (int i = 0; i < 16; i++) csum[i] = 0.0f;

#pragma unroll
    for (int fm = 0; fm < 2; fm++)
#pragma unroll
        for (int fn = 0; fn < 8; fn++) {
#pragma unroll
            for (int i = 0; i < 2; i++) {          // i: row-half of quad
                float t0 = c[fm][fn][i * 2 + 0] * CEXP;   // j=0
                float t1 = c[fm][fn][i * 2 + 1] * CEXP;   // j=1
                __half2 h = h2exp2(__floats2half2_rn(t0, t1));
                float e0 = __low2float(h);
                float e1 = __high2float(h);
                rsum[fm][i] += e0 + e1;
                csum[fn * 2 + 0] += e0;
                csum[fn * 2 + 1] += e1;
            }
            if (diag_cta) {
#pragma unroll
                for (int q = 0; q < 4; q++) {
                    int i = q >> 1, j = q & 1;
                    int gr = rowBase + warp_m * 32 + fm * 16 + i * 8 + (lane >> 2);
                    int gc = colBase + warp_n * 64 + fn * 8 + (lane & 3) * 2 + j;
                    if (gr == gc)
                        g_diag[p * BATCH + gr] = c[fm][fn][q] * INV_T;
                }
            }
        }

#pragma unroll
    for (int fm = 0; fm < 2; fm++)
#pragma unroll
        for (int i = 0; i < 2; i++) {
            float v = rsum[fm][i];
            v += __shfl_xor_sync(0xFFFFFFFFu, v, 1);
            v += __shfl_xor_sync(0xFFFFFFFFu, v, 2);
            if ((lane & 3) == 0) {
                int gr = rowBase + warp_m * 32 + fm * 16 + i * 8 + (lane >> 2);
                atomicAdd(&g_rowsum[p * BATCH + gr], v);
            }
        }

#pragma unroll
    for (int t = 0; t < 16; t++) {
        float v = csum[t];
        v += __shfl_xor_sync(0xFFFFFFFFu, v, 4);
        v += __shfl_xor_sync(0xFFFFFFFFu, v, 8);
        v += __shfl_xor_sync(0xFFFFFFFFu, v, 16);
        if (lane < 4) {
            int fn = t >> 1, j = t & 1;
            int gc = colBase + warp_n * 64 + fn * 8 + lane * 2 + j;
            atomicAdd(&g_colsum[p * BATCH + gc], v);
        }
    }
}

// ---------------------------------------------------------------------------
// Kernel 3: per-(pair,b) loss terms + global mean (__logf = MUFU lg2)
// ---------------------------------------------------------------------------
__global__ void finalize_kernel(float* __restrict__ out) {
    int idx = blockIdx.x * 256 + threadIdx.x;
    float v = 0.0f;
    if (idx < NPAIR * BATCH)
        v = 0.5f * (__logf(g_rowsum[idx]) + __logf(g_colsum[idx])) - g_diag[idx];
#pragma unroll
    for (int o = 16; o > 0; o >>= 1)
        v += __shfl_xor_sync(0xFFFFFFFFu, v, o);
    __shared__ float ws[8];
    int w = threadIdx.x >> 5, l = threadIdx.x & 31;
    if (l == 0) ws[w] = v;
    __syncthreads();
    if (threadIdx.x == 0) {
        float s = 0.0f;
#pragma unroll
        for (int i = 0; i < 8; i++) s += ws[i];
        atomicAdd(out, s * (1.0f / ((float)BATCH * (float)NPAIR)));
    }
}

// ---------------------------------------------------------------------------
extern "C" void kernel_launch(void* const* d_in, const int* in_sizes, int n_in,
                              void* d_out, int out_size) {
    const float* z0 = (const float*)d_in[0];
    const float* z1 = (const float*)d_in[1];
    const float* z2 = (const float*)d_in[2];
    const float* z3 = (const float*)d_in[3];
    float* out = (float*)d_out;
    (void)in_sizes; (void)n_in; (void)out_size;

    cudaFuncSetAttribute(pair_mma_kernel,
                         cudaFuncAttributeMaxDynamicSharedMemorySize, SMEM_TOTAL);

    // launch indices: 0 zero_row, 1 zero_col, 2 normalize,
    // 3 pair_mma (ncu capture), 4 finalize
    zero_row_kernel<<<(NPAIR * BATCH + 255) / 256, 256>>>(out);
    zero_col_kernel<<<(NPAIR * BATCH + 255) / 256, 256>>>();
    normalize_kernel<<<(2 * BATCH) / 8, 256>>>(z0, z1, z2, z3);
    dim3 ggrid(32, 32, NPAIR);
    pair_mma_kernel<<<ggrid, 256, SMEM_TOTAL>>>();
    finalize_kernel<<<(NPAIR * BATCH + 255) / 256, 256>>>(out);
}

// round 12
// speedup vs baseline: 1.5638x; 1.0032x over previous
#include <cuda_runtime.h>
#include <cuda_bf16.h>
#include <math.h>
#include <stdint.h>

#define BATCH 4096
#define DIM   256
#define NPAIR 6
#define INV_T 10.0f

__constant__ int c_pi[NPAIR] = {0, 0, 0, 1, 1, 2};
__constant__ int c_pj[NPAIR] = {1, 2, 3, 2, 3, 3};

// Scratch (allocs forbidden)
__device__ __nv_bfloat16 g_znb[4 * BATCH * DIM];   // normalized views, bf16
__device__ float g_rowsum[NPAIR * BATCH];
__device__ float g_colsum[NPAIR * BATCH];
__device__ float g_diag[NPAIR * BATCH];

// ---------------------------------------------------------------------------
__device__ __forceinline__ uint32_t smem_u32(const void* p) {
    uint32_t a;
    asm("{ .reg .u64 t; cvta.to.shared.u64 t, %1; cvt.u32.u64 %0, t; }"
        : "=r"(a) : "l"(p));
    return a;
}

#define CP_ASYNC16(smem, gptr) \
    asm volatile("cp.async.cg.shared.global [%0], [%1], 16;" \
                 :: "r"(smem), "l"(gptr) : "memory")
#define CP_COMMIT() asm volatile("cp.async.commit_group;" ::: "memory")
#define CP_WAIT(n)  asm volatile("cp.async.wait_group %0;" :: "n"(n) : "memory")

#define LDMATRIX_X4(r0, r1, r2, r3, addr) \
    asm volatile("ldmatrix.sync.aligned.m8n8.x4.shared.b16 {%0,%1,%2,%3}, [%4];" \
                 : "=r"(r0), "=r"(r1), "=r"(r2), "=r"(r3) : "r"(addr))

#define MMA_BF16(c, a, b) \
    asm volatile("mma.sync.aligned.m16n8k16.row.col.f32.bf16.bf16.f32 " \
                 "{%0,%1,%2,%3}, {%4,%5,%6,%7}, {%8,%9}, {%0,%1,%2,%3};" \
                 : "+f"((c)[0]), "+f"((c)[1]), "+f"((c)[2]), "+f"((c)[3]) \
                 : "r"((a)[0]), "r"((a)[1]), "r"((a)[2]), "r"((a)[3]), \
                   "r"((b)[0]), "r"((b)[1]))

// ---------------------------------------------------------------------------
// Kernel 1: zero accumulators (fused) + L2-normalize -> bf16.
// Two rows per warp (MLP 4).
// ---------------------------------------------------------------------------
__global__ void normalize_kernel(const float* __restrict__ z0,
                                 const float* __restrict__ z1,
                                 const float* __restrict__ z2,
                                 const float* __restrict__ z3,
                                 float* __restrict__ out) {
    int gidx = blockIdx.x * blockDim.x + threadIdx.x;
    if (gidx < NPAIR * BATCH) {
        g_rowsum[gidx] = 0.0f;
        g_colsum[gidx] = 0.0f;
    }
    if (gidx == 0) out[0] = 0.0f;

    int gwarp = gidx >> 5;                 // 0 .. 2*BATCH-1
    int lane  = threadIdx.x & 31;
    if (gwarp >= 2 * BATCH) return;

    float4 v[2][2];
    float  ss[2];
    const float* srcs[2];
#pragma unroll
    for (int r = 0; r < 2; r++) {
        int fr   = gwarp * 2 + r;          // flat row 0..16383
        int view = fr >> 12;
        int row  = fr & (BATCH - 1);
        const float* src;
        switch (view) {
            case 0: src = z0; break;
            case 1: src = z1; break;
            case 2: src = z2; break;
            default: src = z3; break;
        }
        srcs[r] = src + (size_t)row * DIM;
    }
#pragma unroll
    for (int r = 0; r < 2; r++) {
        const float4* s4 = (const float4*)srcs[r];
        v[r][0] = s4[lane * 2 + 0];
        v[r][1] = s4[lane * 2 + 1];
    }
#pragma unroll
    for (int r = 0; r < 2; r++) {
        float4 a = v[r][0], b = v[r][1];
        ss[r] = a.x * a.x + a.y * a.y + a.z * a.z + a.w * a.w
              + b.x * b.x + b.y * b.y + b.z * b.z + b.w * b.w;
    }
#pragma unroll
    for (int o = 16; o > 0; o >>= 1) {
        ss[0] += __shfl_xor_sync(0xFFFFFFFFu, ss[0], o);
        ss[1] += __shfl_xor_sync(0xFFFFFFFFu, ss[1], o);
    }
#pragma unroll
    for (int r = 0; r < 2; r++) {
        float inv = 1.0f / fmaxf(sqrtf(ss[r]), 1e-8f);
        float4 a = v[r][0], b = v[r][1];
        __nv_bfloat162 p0 = __floats2bfloat162_rn(a.x * inv, a.y * inv);
        __nv_bfloat162 p1 = __floats2bfloat162_rn(a.z * inv, a.w * inv);
        __nv_bfloat162 p2 = __floats2bfloat162_rn(b.x * inv, b.y * inv);
        __nv_bfloat162 p3 = __floats2bfloat162_rn(b.z * inv, b.w * inv);
        uint4 o4;
        o4.x = reinterpret_cast<uint32_t&>(p0);
        o4.y = reinterpret_cast<uint32_t&>(p1);
        o4.z = reinterpret_cast<uint32_t&>(p2);
        o4.w = reinterpret_cast<uint32_t&>(p3);
        int fr = gwarp * 2 + r;
        uint4* dst = (uint4*)(g_znb + (size_t)fr * DIM);
        dst[lane] = o4;
    }
}

// ---------------------------------------------------------------------------
// Kernel 2: R6-winner bf16 mma.sync pair GEMM + phase stagger.
// CTA tile 128x128, 8 warps 4x2, warp tile 32x64. K chunks of 64, 3-stage
// cp.async pipeline, one barrier per chunk. Odd-checkerboard CTAs delay
// ~700ns before the prologue so the two co-resident CTAs per SM run
// phase-offset: one covers the other's prologue-drain/epilogue tensor-idle.
// SMEM chunk layout (128x64 bf16, 16 KB):
//   element (row, k): byte = row*128 + ((k/8) ^ (row&7))*16 + (k%8)*2
// ---------------------------------------------------------------------------
#define KC 64
#define CHUNK_BYTES (128 * 128)     // 16 KB
#define NSTAGE 3
#define SMEM_TOTAL (2 * NSTAGE * CHUNK_BYTES)   // 96 KB

__device__ __forceinline__ void load_chunk(uint32_t s_base,
                                           const __nv_bfloat16* __restrict__ src,
                                           int kc, int tid) {
#pragma unroll
    for (int it = 0; it < 4; it++) {
        int idx = it * 256 + tid;         // 0..1023
        int row = idx >> 3;
        int c   = idx & 7;
        const __nv_bfloat16* g = src + (size_t)row * DIM + kc * KC + c * 8;
        uint32_t s = s_base + row * 128 + ((c ^ (row & 7)) << 4);
        CP_ASYNC16(s, g);
    }
}

__global__ void __launch_bounds__(256) pair_mma_kernel() {
    extern __shared__ char smraw[];
    uint32_t sbase = smem_u32(smraw);

    int tid = threadIdx.x;
    int w = tid >> 5, lane = tid & 31;
    int warp_m = w & 3;                 // 0..3 -> 32 rows each
    int warp_n = w >> 2;                // 0..1 -> 64 cols each

    int p = blockIdx.z;
    int rowBase = blockIdx.y * 128;
    int colBase = blockIdx.x * 128;

    // Phase stagger: desynchronize co-resident CTAs (checkerboard parity).
    if ((blockIdx.x + blockIdx.y + p) & 1) __nanosleep(700);

    const __nv_bfloat16* Asrc = g_znb + ((size_t)c_pi[p] * BATCH + rowBase) * DIM;
    const __nv_bfloat16* Bsrc = g_znb + ((size_t)c_pj[p] * BATCH + colBase) * DIM;

    uint32_t sA[NSTAGE], sB[NSTAGE];
#pragma unroll
    for (int s = 0; s < NSTAGE; s++) {
        sA[s] = sbase + s * CHUNK_BYTES;
        sB[s] = sbase + (NSTAGE + s) * CHUNK_BYTES;
    }

    float c[2][8][4];
#pragma unroll
    for (int i = 0; i < 2; i++)
#pragma unroll
        for (int j = 0; j < 8; j++)
#pragma unroll
            for (int q = 0; q < 4; q++) c[i][j][q] = 0.0f;

    int ar = warp_m * 32 + (lane & 15);
    int akg = lane >> 4;
    int bn = warp_n * 64 + ((lane >> 4) << 3) + (lane & 7);
    int bkg = (lane >> 3) & 1;

    load_chunk(sA[0], Asrc, 0, tid);
    load_chunk(sB[0], Bsrc, 0, tid);
    CP_COMMIT();
    load_chunk(sA[1], Asrc, 1, tid);
    load_chunk(sB[1], Bsrc, 1, tid);
    CP_COMMIT();

#pragma unroll
    for (int kc = 0; kc < 4; kc++) {
        if (kc < 3) { CP_WAIT(1); } else { CP_WAIT(0); }
        __syncthreads();
        if (kc < 2) {
            int nb = (kc + 2) % NSTAGE;
            load_chunk(sA[nb], Asrc, kc + 2, tid);
            load_chunk(sB[nb], Bsrc, kc + 2, tid);
            CP_COMMIT();
        }
        int buf = kc % NSTAGE;

#pragma unroll
        for (int kk = 0; kk < 4; kk++) {
            uint32_t a[2][4];
#pragma unroll
            for (int fm = 0; fm < 2; fm++) {
                int r = ar + fm * 16;
                int kg = kk * 2 + akg;
                uint32_t addr = sA[buf] + r * 128 + ((kg ^ (r & 7)) << 4);
                LDMATRIX_X4(a[fm][0], a[fm][1], a[fm][2], a[fm][3], addr);
            }
            uint32_t b[4][4];
#pragma unroll
            for (int nb = 0; nb < 4; nb++) {
                int n = bn + nb * 16;
                int kg = kk * 2 + bkg;
                uint32_t addr = sB[buf] + n * 128 + ((kg ^ (n & 7)) << 4);
                LDMATRIX_X4(b[nb][0], b[nb][1], b[nb][2], b[nb][3], addr);
            }
#pragma unroll
            for (int fm = 0; fm < 2; fm++)
#pragma unroll
                for (int nb = 0; nb < 4; nb++) {
                    uint32_t bf0[2] = {b[nb][0], b[nb][1]};
                    uint32_t bf1[2] = {b[nb][2], b[nb][3]};
                    MMA_BF16(c[fm][nb * 2 + 0], a[fm], bf0);
                    MMA_BF16(c[fm][nb * 2 + 1], a[fm], bf1);
                }
        }
    }

    // ------------------- epilogue (register-only, proven R6 form) ----------
    bool diag_cta = (rowBase == colBase);
    float rsum[2][2] = {{0, 0}, {0, 0}};
    float csum[16];
#pragma unroll
    for (int i = 0; i < 16; i++) csum[i] = 0.0f;

#pragma unroll
    for (int fm = 0; fm < 2; fm++)
#pragma unroll
        for (int fn = 0; fn < 8; fn++)
#pragma unroll
            for (int q = 0; q < 4; q++) {
                int i = q >> 1, j = q & 1;
                float s = c[fm][fn][q] * INV_T;
                float e = __expf(s);
                rsum[fm][i] += e;
                csum[fn * 2 + j] += e;
                if (diag_cta) {
                    int gr = rowBase + warp_m * 32 + fm * 16 + i * 8 + (lane >> 2);
                    int gc = colBase + warp_n * 64 + fn * 8 + (lane & 3) * 2 + j;
                    if (gr == gc) g_diag[p * BATCH + gr] = s;
                }
            }

#pragma unroll
    for (int fm = 0; fm < 2; fm++)
#pragma unroll
        for (int i = 0; i < 2; i++) {
            float v = rsum[fm][i];
            v += __shfl_xor_sync(0xFFFFFFFFu, v, 1);
            v += __shfl_xor_sync(0xFFFFFFFFu, v, 2);
            if ((lane & 3) == 0) {
                int gr = rowBase + warp_m * 32 + fm * 16 + i * 8 + (lane >> 2);
                atomicAdd(&g_rowsum[p * BATCH + gr], v);
            }
        }

#pragma unroll
    for (int t = 0; t < 16; t++) {
        float v = csum[t];
        v += __shfl_xor_sync(0xFFFFFFFFu, v, 4);
        v += __shfl_xor_sync(0xFFFFFFFFu, v, 8);
        v += __shfl_xor_sync(0xFFFFFFFFu, v, 16);
        if (lane < 4) {
            int fn = t >> 1, j = t & 1;
            int gc = colBase + warp_n * 64 + fn * 8 + lane * 2 + j;
            atomicAdd(&g_colsum[p * BATCH + gc], v);
        }
    }
}

// ---------------------------------------------------------------------------
// Kernel 3: per-(pair,b) loss terms + global mean (__logf = MUFU lg2)
// ---------------------------------------------------------------------------
__global__ void finalize_kernel(float* __restrict__ out) {
    int idx = blockIdx.x * 256 + threadIdx.x;
    float v = 0.0f;
    if (idx < NPAIR * BATCH)
        v = 0.5f * (__logf(g_rowsum[idx]) + __logf(g_colsum[idx])) - g_diag[idx];
#pragma unroll
    for (int o = 16; o > 0; o >>= 1)
        v += __shfl_xor_sync(0xFFFFFFFFu, v, o);
    __shared__ float ws[8];
    int w = threadIdx.x >> 5, l = threadIdx.x & 31;
    if (l == 0) ws[w] = v;
    __syncthreads();
    if (threadIdx.x == 0) {
        float s = 0.0f;
#pragma unroll
        for (int i = 0; i < 8; i++) s += ws[i];
        atomicAdd(out, s * (1.0f / ((float)BATCH * (float)NPAIR)));
    }
}

// ---------------------------------------------------------------------------
extern "C" void kernel_launch(void* const* d_in, const int* in_sizes, int n_in,
                              void* d_out, int out_size) {
    const float* z0 = (const float*)d_in[0];
    const float* z1 = (const float*)d_in[1];
    const float* z2 = (const float*)d_in[2];
    const float* z3 = (const float*)d_in[3];
    float* out = (float*)d_out;
    (void)in_sizes; (void)n_in; (void)out_size;

    cudaFuncSetAttribute(pair_mma_kernel,
                         cudaFuncAttributeMaxDynamicSharedMemorySize, SMEM_TOTAL);

    normalize_kernel<<<(2 * BATCH) / 8, 256>>>(z0, z1, z2, z3, out);
    dim3 ggrid(32, 32, NPAIR);
    pair_mma_kernel<<<ggrid, 256, SMEM_TOTAL>>>();
    finalize_kernel<<<(NPAIR * BATCH + 255) / 256, 256>>>(out);
}

// round 14
// speedup vs baseline: 1.6179x; 1.0346x over previous
#include <cuda_runtime.h>
#include <cuda_bf16.h>
#include <math.h>
#include <stdint.h>

#define BATCH 4096
#define DIM   256
#define NPAIR 6
#define INV_T 10.0f

__constant__ int c_pi[NPAIR] = {0, 0, 0, 1, 1, 2};
__constant__ int c_pj[NPAIR] = {1, 2, 3, 2, 3, 3};

// Scratch (allocs forbidden)
__device__ __nv_bfloat16 g_znb[4 * BATCH * DIM];   // normalized views, bf16
__device__ float g_rowsum[NPAIR * BATCH];
__device__ float g_colsum[NPAIR * BATCH];
__device__ float g_diag[NPAIR * BATCH];

// ---------------------------------------------------------------------------
__device__ __forceinline__ uint32_t smem_u32(const void* p) {
    uint32_t a;
    asm("{ .reg .u64 t; cvta.to.shared.u64 t, %1; cvt.u32.u64 %0, t; }"
        : "=r"(a) : "l"(p));
    return a;
}

#define CP_ASYNC16(smem, gptr) \
    asm volatile("cp.async.cg.shared.global [%0], [%1], 16;" \
                 :: "r"(smem), "l"(gptr) : "memory")
#define CP_COMMIT() asm volatile("cp.async.commit_group;" ::: "memory")
#define CP_WAIT(n)  asm volatile("cp.async.wait_group %0;" :: "n"(n) : "memory")

#define LDMATRIX_X4(r0, r1, r2, r3, addr) \
    asm volatile("ldmatrix.sync.aligned.m8n8.x4.shared.b16 {%0,%1,%2,%3}, [%4];" \
                 : "=r"(r0), "=r"(r1), "=r"(r2), "=r"(r3) : "r"(addr))

#define MMA_BF16(c, a, b) \
    asm volatile("mma.sync.aligned.m16n8k16.row.col.f32.bf16.bf16.f32 " \
                 "{%0,%1,%2,%3}, {%4,%5,%6,%7}, {%8,%9}, {%0,%1,%2,%3};" \
                 : "+f"((c)[0]), "+f"((c)[1]), "+f"((c)[2]), "+f"((c)[3]) \
                 : "r"((a)[0]), "r"((a)[1]), "r"((a)[2]), "r"((a)[3]), \
                   "r"((b)[0]), "r"((b)[1]))

// ---------------------------------------------------------------------------
// Kernel 1: zero accumulators (fused) + L2-normalize -> bf16.
// Two rows per warp (MLP 4).
// ---------------------------------------------------------------------------
__global__ void normalize_kernel(const float* __restrict__ z0,
                                 const float* __restrict__ z1,
                                 const float* __restrict__ z2,
                                 const float* __restrict__ z3,
                                 float* __restrict__ out) {
    int gidx = blockIdx.x * blockDim.x + threadIdx.x;
    if (gidx < NPAIR * BATCH) {
        g_rowsum[gidx] = 0.0f;
        g_colsum[gidx] = 0.0f;
    }
    if (gidx == 0) out[0] = 0.0f;

    int gwarp = gidx >> 5;                 // 0 .. 2*BATCH-1
    int lane  = threadIdx.x & 31;
    if (gwarp >= 2 * BATCH) return;

    float4 v[2][2];
    float  ss[2];
    const float* srcs[2];
#pragma unroll
    for (int r = 0; r < 2; r++) {
        int fr   = gwarp * 2 + r;          // flat row 0..16383
        int view = fr >> 12;
        int row  = fr & (BATCH - 1);
        const float* src;
        switch (view) {
            case 0: src = z0; break;
            case 1: src = z1; break;
            case 2: src = z2; break;
            default: src = z3; break;
        }
        srcs[r] = src + (size_t)row * DIM;
    }
#pragma unroll
    for (int r = 0; r < 2; r++) {
        const float4* s4 = (const float4*)srcs[r];
        v[r][0] = s4[lane * 2 + 0];
        v[r][1] = s4[lane * 2 + 1];
    }
#pragma unroll
    for (int r = 0; r < 2; r++) {
        float4 a = v[r][0], b = v[r][1];
        ss[r] = a.x * a.x + a.y * a.y + a.z * a.z + a.w * a.w
              + b.x * b.x + b.y * b.y + b.z * b.z + b.w * b.w;
    }
#pragma unroll
    for (int o = 16; o > 0; o >>= 1) {
        ss[0] += __shfl_xor_sync(0xFFFFFFFFu, ss[0], o);
        ss[1] += __shfl_xor_sync(0xFFFFFFFFu, ss[1], o);
    }
#pragma unroll
    for (int r = 0; r < 2; r++) {
        float inv = 1.0f / fmaxf(sqrtf(ss[r]), 1e-8f);
        float4 a = v[r][0], b = v[r][1];
        __nv_bfloat162 p0 = __floats2bfloat162_rn(a.x * inv, a.y * inv);
        __nv_bfloat162 p1 = __floats2bfloat162_rn(a.z * inv, a.w * inv);
        __nv_bfloat162 p2 = __floats2bfloat162_rn(b.x * inv, b.y * inv);
        __nv_bfloat162 p3 = __floats2bfloat162_rn(b.z * inv, b.w * inv);
        uint4 o4;
        o4.x = reinterpret_cast<uint32_t&>(p0);
        o4.y = reinterpret_cast<uint32_t&>(p1);
        o4.z = reinterpret_cast<uint32_t&>(p2);
        o4.w = reinterpret_cast<uint32_t&>(p3);
        int fr = gwarp * 2 + r;
        uint4* dst = (uint4*)(g_znb + (size_t)fr * DIM);
        dst[lane] = o4;
    }
}

// ---------------------------------------------------------------------------
// Kernel 2: R6-winner bf16 mma.sync pair GEMM (verbatim).
// CTA tile 128x128, 8 warps 4x2, warp tile 32x64. K chunks of 64, 3-stage
// cp.async pipeline, one barrier per chunk.
// SMEM chunk layout (128x64 bf16, 16 KB):
//   element (row, k): byte = row*128 + ((k/8) ^ (row&7))*16 + (k%8)*2
// ---------------------------------------------------------------------------
#define KC 64
#define CHUNK_BYTES (128 * 128)     // 16 KB
#define NSTAGE 3
#define SMEM_TOTAL (2 * NSTAGE * CHUNK_BYTES)   // 96 KB

__device__ __forceinline__ void load_chunk(uint32_t s_base,
                                           const __nv_bfloat16* __restrict__ src,
                                           int kc, int tid) {
#pragma unroll
    for (int it = 0; it < 4; it++) {
        int idx = it * 256 + tid;         // 0..1023
        int row = idx >> 3;
        int c   = idx & 7;
        const __nv_bfloat16* g = src + (size_t)row * DIM + kc * KC + c * 8;
        uint32_t s = s_base + row * 128 + ((c ^ (row & 7)) << 4);
        CP_ASYNC16(s, g);
    }
}

__global__ void __launch_bounds__(256) pair_mma_kernel() {
    extern __shared__ char smraw[];
    uint32_t sbase = smem_u32(smraw);

    int tid = threadIdx.x;
    int w = tid >> 5, lane = tid & 31;
    int warp_m = w & 3;                 // 0..3 -> 32 rows each
    int warp_n = w >> 2;                // 0..1 -> 64 cols each

    int p = blockIdx.z;
    int rowBase = blockIdx.y * 128;
    int colBase = blockIdx.x * 128;
    const __nv_bfloat16* Asrc = g_znb + ((size_t)c_pi[p] * BATCH + rowBase) * DIM;
    const __nv_bfloat16* Bsrc = g_znb + ((size_t)c_pj[p] * BATCH + colBase) * DIM;

    uint32_t sA[NSTAGE], sB[NSTAGE];
#pragma unroll
    for (int s = 0; s < NSTAGE; s++) {
        sA[s] = sbase + s * CHUNK_BYTES;
        sB[s] = sbase + (NSTAGE + s) * CHUNK_BYTES;
    }

    float c[2][8][4];
#pragma unroll
    for (int i = 0; i < 2; i++)
#pragma unroll
        for (int j = 0; j < 8; j++)
#pragma unroll
            for (int q = 0; q < 4; q++) c[i][j][q] = 0.0f;

    int ar = warp_m * 32 + (lane & 15);
    int akg = lane >> 4;
    int bn = warp_n * 64 + ((lane >> 4) << 3) + (lane & 7);
    int bkg = (lane >> 3) & 1;

    load_chunk(sA[0], Asrc, 0, tid);
    load_chunk(sB[0], Bsrc, 0, tid);
    CP_COMMIT();
    load_chunk(sA[1], Asrc, 1, tid);
    load_chunk(sB[1], Bsrc, 1, tid);
    CP_COMMIT();

#pragma unroll
    for (int kc = 0; kc < 4; kc++) {
        if (kc < 3) { CP_WAIT(1); } else { CP_WAIT(0); }
        __syncthreads();
        if (kc < 2) {
            int nb = (kc + 2) % NSTAGE;
            load_chunk(sA[nb], Asrc, kc + 2, tid);
            load_chunk(sB[nb], Bsrc, kc + 2, tid);
            CP_COMMIT();
        }
        int buf = kc % NSTAGE;

#pragma unroll
        for (int kk = 0; kk < 4; kk++) {
            uint32_t a[2][4];
#pragma unroll
            for (int fm = 0; fm < 2; fm++) {
                int r = ar + fm * 16;
                int kg = kk * 2 + akg;
                uint32_t addr = sA[buf] + r * 128 + ((kg ^ (r & 7)) << 4);
                LDMATRIX_X4(a[fm][0], a[fm][1], a[fm][2], a[fm][3], addr);
            }
            uint32_t b[4][4];
#pragma unroll
            for (int nb = 0; nb < 4; nb++) {
                int n = bn + nb * 16;
                int kg = kk * 2 + bkg;
                uint32_t addr = sB[buf] + n * 128 + ((kg ^ (n & 7)) << 4);
                LDMATRIX_X4(b[nb][0], b[nb][1], b[nb][2], b[nb][3], addr);
            }
#pragma unroll
            for (int fm = 0; fm < 2; fm++)
#pragma unroll
                for (int nb = 0; nb < 4; nb++) {
                    uint32_t bf0[2] = {b[nb][0], b[nb][1]};
                    uint32_t bf1[2] = {b[nb][2], b[nb][3]};
                    MMA_BF16(c[fm][nb * 2 + 0], a[fm], bf0);
                    MMA_BF16(c[fm][nb * 2 + 1], a[fm], bf1);
                }
        }
    }

    // ------------------- epilogue (register-only, proven R6 form) ----------
    bool diag_cta = (rowBase == colBase);
    float rsum[2][2] = {{0, 0}, {0, 0}};
    float csum[16];
#pragma unroll
    for (int i = 0; i < 16; i++) csum[i] = 0.0f;

#pragma unroll
    for (int fm = 0; fm < 2; fm++)
#pragma unroll
        for (int fn = 0; fn < 8; fn++)
#pragma unroll
            for (int q = 0; q < 4; q++) {
                int i = q >> 1, j = q & 1;
                float s = c[fm][fn][q] * INV_T;
                float e = __expf(s);
                rsum[fm][i] += e;
                csum[fn * 2 + j] += e;
                if (diag_cta) {
                    int gr = rowBase + warp_m * 32 + fm * 16 + i * 8 + (lane >> 2);
                    int gc = colBase + warp_n * 64 + fn * 8 + (lane & 3) * 2 + j;
                    if (gr == gc) g_diag[p * BATCH + gr] = s;
                }
            }

#pragma unroll
    for (int fm = 0; fm < 2; fm++)
#pragma unroll
        for (int i = 0; i < 2; i++) {
            float v = rsum[fm][i];
            v += __shfl_xor_sync(0xFFFFFFFFu, v, 1);
            v += __shfl_xor_sync(0xFFFFFFFFu, v, 2);
            if ((lane & 3) == 0) {
                int gr = rowBase + warp_m * 32 + fm * 16 + i * 8 + (lane >> 2);
                atomicAdd(&g_rowsum[p * BATCH + gr], v);
            }
        }

#pragma unroll
    for (int t = 0; t < 16; t++) {
        float v = csum[t];
        v += __shfl_xor_sync(0xFFFFFFFFu, v, 4);
        v += __shfl_xor_sync(0xFFFFFFFFu, v, 8);
        v += __shfl_xor_sync(0xFFFFFFFFu, v, 16);
        if (lane < 4) {
            int fn = t >> 1, j = t & 1;
            int gc = colBase + warp_n * 64 + fn * 8 + lane * 2 + j;
            atomicAdd(&g_colsum[p * BATCH + gc], v);
        }
    }
}

// ---------------------------------------------------------------------------
// Kernel 3: per-(pair,b) loss terms + global mean (__logf = MUFU lg2)
// ---------------------------------------------------------------------------
__global__ void finalize_kernel(float* __restrict__ out) {
    int idx = blockIdx.x * 256 + threadIdx.x;
    float v = 0.0f;
    if (idx < NPAIR * BATCH)
        v = 0.5f * (__logf(g_rowsum[idx]) + __logf(g_colsum[idx])) - g_diag[idx];
#pragma unroll
    for (int o = 16; o > 0; o >>= 1)
        v += __shfl_xor_sync(0xFFFFFFFFu, v, o);
    __shared__ float ws[8];
    int w = threadIdx.x >> 5, l = threadIdx.x & 31;
    if (l == 0) ws[w] = v;
    __syncthreads();
    if (threadIdx.x == 0) {
        float s = 0.0f;
#pragma unroll
        for (int i = 0; i < 8; i++) s += ws[i];
        atomicAdd(out, s * (1.0f / ((float)BATCH * (float)NPAIR)));
    }
}

// ---------------------------------------------------------------------------
extern "C" void kernel_launch(void* const* d_in, const int* in_sizes, int n_in,
                              void* d_out, int out_size) {
    const float* z0 = (const float*)d_in[0];
    const float* z1 = (const float*)d_in[1];
    const float* z2 = (const float*)d_in[2];
    const float* z3 = (const float*)d_in[3];
    float* out = (float*)d_out;
    (void)in_sizes; (void)n_in; (void)out_size;

    cudaFuncSetAttribute(pair_mma_kernel,
                         cudaFuncAttributeMaxDynamicSharedMemorySize, SMEM_TOTAL);

    normalize_kernel<<<(2 * BATCH) / 8, 256>>>(z0, z1, z2, z3, out);
    dim3 ggrid(32, 32, NPAIR);
    pair_mma_kernel<<<ggrid, 256, SMEM_TOTAL>>>();
    finalize_kernel<<<(NPAIR * BATCH + 255) / 256, 256>>>(out);
}